// round 12
// baseline (speedup 1.0000x reference)
#include <cuda_runtime.h>
#include <cuda_bf16.h>
#include <cstdint>

#define D_IN    3072
#define H1      32
#define OUT_N   10
#define M_TILE  64
#define KC      64              // fp32 K per chunk
#define NKB     (D_IN / KC)    // 48
#define NT      128
#define N_ROWS  32768

// byte offsets from 1024-aligned smem base
#define SM_A      0             // 2 x 16384  (A bf16: 64 rows x [hi 128B | lo 128B])
#define SM_B      32768         // 2 x 8192   (B bf16: 32 rows x [hi | lo])
#define SM_SUM    49152         // 64 f
#define SM_SQ     49408         // 64 f
#define SM_W2     49664         // 32*32 f
#define SM_W3     53760         // 10*32 f
#define SM_B1     55040
#define SM_B2     55168
#define SM_B3     55296
#define SM_SC     55424
#define SM_BYTES  (55552 + 1024)

#define SWZ(o) ((o) ^ (((o) >> 3) & 0x70))

// ---------------------------------------------------------------------------
// helpers
// ---------------------------------------------------------------------------
__device__ __forceinline__ uint32_t smem_u32(const void* p) {
    uint32_t a;
    asm("{ .reg .u64 t; cvta.to.shared.u64 t, %1; cvt.u32.u64 %0, t; }"
        : "=r"(a) : "l"(p));
    return a;
}
__device__ __forceinline__ unsigned long long pk(float a, float b) {
    unsigned long long r;
    asm("mov.b64 %0, {%1, %2};" : "=l"(r) : "f"(a), "f"(b));
    return r;
}
__device__ __forceinline__ void add2(unsigned long long& d, unsigned long long a) {
    asm("add.rn.f32x2 %0, %1, %0;" : "+l"(d) : "l"(a));
}
__device__ __forceinline__ void fma2(unsigned long long& d,
                                     unsigned long long a, unsigned long long b) {
    asm("fma.rn.f32x2 %0, %1, %2, %0;" : "+l"(d) : "l"(a), "l"(b));
}
__device__ __forceinline__ float lohi(unsigned long long v) {
    union { unsigned long long u; float2 f; } t; t.u = v;
    return t.f.x + t.f.y;
}
__device__ __forceinline__ void sts128(uint32_t addr, const uint32_t* r) {
    asm volatile("st.shared.v4.b32 [%0], {%1,%2,%3,%4};"
                 :: "r"(addr), "r"(r[0]), "r"(r[1]), "r"(r[2]), "r"(r[3]) : "memory");
}
// 8 consecutive fp32 -> 4 u32 bf16-hi pairs + 4 u32 bf16-lo pairs (k order kept)
__device__ __forceinline__ void cvt8(float4 a, float4 b, uint32_t* h, uint32_t* l) {
    float v[8] = {a.x, a.y, a.z, a.w, b.x, b.y, b.z, b.w};
    #pragma unroll
    for (int k = 0; k < 4; k++) {
        float v0 = v[2 * k], v1 = v[2 * k + 1];
        uint32_t hw;
        asm("cvt.rn.bf16x2.f32 %0, %1, %2;" : "=r"(hw) : "f"(v1), "f"(v0)); // lo = v0
        float h0 = __uint_as_float(hw << 16);
        float h1 = __uint_as_float(hw & 0xffff0000u);
        float l0 = v0 - h0, l1 = v1 - h1;
        uint32_t lw;
        asm("cvt.rn.bf16x2.f32 %0, %1, %2;" : "=r"(lw) : "f"(l1), "f"(l0));
        h[k] = hw; l[k] = lw;
    }
}
__device__ __forceinline__ void ldm4(uint32_t* r, uint32_t addr) {
    asm volatile("ldmatrix.sync.aligned.m8n8.x4.shared.b16 {%0,%1,%2,%3}, [%4];"
                 : "=r"(r[0]), "=r"(r[1]), "=r"(r[2]), "=r"(r[3]) : "r"(addr));
}
__device__ __forceinline__ void mma_bf16(float* d, const uint32_t* a,
                                         const uint32_t* b) {
    asm volatile(
        "mma.sync.aligned.m16n8k16.row.col.f32.bf16.bf16.f32 "
        "{%0,%1,%2,%3}, {%4,%5,%6,%7}, {%8,%9}, {%0,%1,%2,%3};"
        : "+f"(d[0]), "+f"(d[1]), "+f"(d[2]), "+f"(d[3])
        : "r"(a[0]), "r"(a[1]), "r"(a[2]), "r"(a[3]), "r"(b[0]), "r"(b[1]));
}

// ---------------------------------------------------------------------------
// Fused: stats + w1-rowsums + bf16-split HMMA GEMM + norm + L1/L2/L3
// ---------------------------------------------------------------------------
__global__ __launch_bounds__(NT, 4) void fused_kernel(
    const float* __restrict__ x,  const float* __restrict__ w1,
    const float* __restrict__ b1, const float* __restrict__ w2,
    const float* __restrict__ b2, const float* __restrict__ w3,
    const float* __restrict__ b3, float* __restrict__ out)
{
    extern __shared__ char smraw[];
    const uint32_t sb_u = smem_u32(smraw);
    const uint32_t sb   = (sb_u + 1023u) & ~1023u;
    char* smb = smraw + (sb - sb_u);

    float* sumS = (float*)(smb + SM_SUM);
    float* sqS  = (float*)(smb + SM_SQ);
    float* w2S  = (float*)(smb + SM_W2);
    float* w3S  = (float*)(smb + SM_W3);
    float* b1S  = (float*)(smb + SM_B1);
    float* b2S  = (float*)(smb + SM_B2);
    float* b3S  = (float*)(smb + SM_B3);
    float* ScS  = (float*)(smb + SM_SC);

    const int tid  = threadIdx.x;
    const int wid  = tid >> 5;
    const int lane = tid & 31;
    const int seg  = tid & 7;           // 8-fp32 segment within 64-K chunk
    const int rgrp = tid >> 3;          // 0..15
    const size_t rowbase = (size_t)blockIdx.x * M_TILE;

    // small weights to smem
    for (int i = tid; i < H1 * H1; i += NT)    w2S[i] = w2[i];
    for (int i = tid; i < OUT_N * H1; i += NT) w3S[i] = w3[i];
    if (tid < H1) { b1S[tid] = b1[tid]; b2S[tid] = b2[tid]; }
    if (tid < OUT_N) b3S[tid] = b3[tid];

    // stats accumulators (f32x2): x rows rgrp+16i, w1 rows rgrp / rgrp+16
    unsigned long long s2[4] = {0,0,0,0}, q2[4] = {0,0,0,0};
    unsigned long long ws2[2] = {0,0};

    // HMMA accumulators: warp owns rows [16*wid, 16*wid+16), 4 n-steps of 8
    float acc[4][4];
    #pragma unroll
    for (int n = 0; n < 4; n++)
        #pragma unroll
        for (int q = 0; q < 4; q++) acc[n][q] = 0.f;

    // ldmatrix address components (constant per thread)
    const uint32_t a_row = (uint32_t)(16 * wid + (lane & 15));
    const uint32_t a_kad = ((lane >> 4) & 1) * 16;
    const uint32_t b_r0  = (uint32_t)((lane & 7) + ((lane >> 4) & 1) * 8);
    const uint32_t b_kad = ((lane >> 3) & 1) * 16;

    // ---- prologue: LDG chunk 0 ----
    float4 xa[4], xb[4], wa[2], wb[2];
    {
        #pragma unroll
        for (int i = 0; i < 4; i++) {
            const float* src = x + (rowbase + rgrp + 16 * i) * D_IN + seg * 8;
            xa[i] = *(const float4*)src;
            xb[i] = *(const float4*)(src + 4);
        }
        #pragma unroll
        for (int i = 0; i < 2; i++) {
            const float* wsrc = w1 + (size_t)(rgrp + 16 * i) * D_IN + seg * 8;
            wa[i] = *(const float4*)wsrc;
            wb[i] = *(const float4*)(wsrc + 4);
        }
    }

    for (int kb = 0; kb < NKB; kb++) {
        const int p = kb & 1;
        const uint32_t Ab = sb + SM_A + p * 16384;
        const uint32_t Bb = sb + SM_B + p * 8192;

        // ---- convert + STS + stats (chunk kb, from regs) ----
        #pragma unroll
        for (int i = 0; i < 4; i++) {
            unsigned long long p0 = pk(xa[i].x, xa[i].y), p1 = pk(xa[i].z, xa[i].w);
            unsigned long long p2 = pk(xb[i].x, xb[i].y), p3 = pk(xb[i].z, xb[i].w);
            add2(s2[i], p0); add2(s2[i], p1); add2(s2[i], p2); add2(s2[i], p3);
            fma2(q2[i], p0, p0); fma2(q2[i], p1, p1);
            fma2(q2[i], p2, p2); fma2(q2[i], p3, p3);

            uint32_t h[4], l[4];
            cvt8(xa[i], xb[i], h, l);
            uint32_t off = (uint32_t)(rgrp + 16 * i) * 128 + seg * 16;
            sts128(Ab + SWZ(off), h);
            sts128(Ab + 8192 + SWZ(off), l);
        }
        #pragma unroll
        for (int i = 0; i < 2; i++) {
            unsigned long long p0 = pk(wa[i].x, wa[i].y), p1 = pk(wa[i].z, wa[i].w);
            unsigned long long p2 = pk(wb[i].x, wb[i].y), p3 = pk(wb[i].z, wb[i].w);
            add2(ws2[i], p0); add2(ws2[i], p1); add2(ws2[i], p2); add2(ws2[i], p3);

            uint32_t h[4], l[4];
            cvt8(wa[i], wb[i], h, l);
            uint32_t off = (uint32_t)(rgrp + 16 * i) * 128 + seg * 16;
            sts128(Bb + SWZ(off), h);
            sts128(Bb + 4096 + SWZ(off), l);
        }
        __syncthreads();

        // ---- prefetch chunk kb+1 (overlaps MMA below) ----
        if (kb + 1 < NKB) {
            const int k0 = (kb + 1) * KC;
            #pragma unroll
            for (int i = 0; i < 4; i++) {
                const float* src = x + (rowbase + rgrp + 16 * i) * D_IN + k0 + seg * 8;
                xa[i] = *(const float4*)src;
                xb[i] = *(const float4*)(src + 4);
            }
            #pragma unroll
            for (int i = 0; i < 2; i++) {
                const float* wsrc = w1 + (size_t)(rgrp + 16 * i) * D_IN + k0 + seg * 8;
                wa[i] = *(const float4*)wsrc;
                wb[i] = *(const float4*)(wsrc + 4);
            }
        }

        // ---- per-warp HMMA on buffer p ----
        #pragma unroll
        for (int j = 0; j < 4; j++) {                       // k16 steps
            uint32_t ah[4], al[4];
            uint32_t aoff = SWZ(a_row * 128 + (uint32_t)j * 32 + a_kad);
            ldm4(ah, Ab + aoff);
            ldm4(al, Ab + 8192 + aoff);
            uint32_t bh[2][4], bl[2][4];
            #pragma unroll
            for (int nb = 0; nb < 2; nb++) {
                uint32_t boff = SWZ(((uint32_t)nb * 16 + b_r0) * 128
                                    + (uint32_t)j * 32 + b_kad);
                ldm4(bh[nb], Bb + boff);
                ldm4(bl[nb], Bb + 4096 + boff);
            }
            #pragma unroll
            for (int n = 0; n < 4; n++) {
                const uint32_t* bhn = &bh[n >> 1][(n & 1) * 2];
                const uint32_t* bln = &bl[n >> 1][(n & 1) * 2];
                mma_bf16(acc[n], ah, bhn);      // hi . hi
                mma_bf16(acc[n], al, bhn);      // lo . hi
                mma_bf16(acc[n], ah, bln);      // hi . lo
            }
        }
        // buffer reuse safety: STS(p^1) next iter happens only after all warps
        // passed this iter's sync, which orders it after MMA(p^1) of kb-1
    }

    // ---- stats reductions over the 8 segments (lanes seg=0..7) ----
    #pragma unroll
    for (int i = 0; i < 4; i++) {
        float s = lohi(s2[i]), q = lohi(q2[i]);
        #pragma unroll
        for (int m = 1; m < 8; m <<= 1) {
            s += __shfl_xor_sync(0xffffffffu, s, m);
            q += __shfl_xor_sync(0xffffffffu, q, m);
        }
        if (seg == 0) { sumS[rgrp + 16 * i] = s; sqS[rgrp + 16 * i] = q; }
    }
    #pragma unroll
    for (int i = 0; i < 2; i++) {
        float s = lohi(ws2[i]);
        #pragma unroll
        for (int m = 1; m < 8; m <<= 1)
            s += __shfl_xor_sync(0xffffffffu, s, m);
        if (seg == 0) ScS[rgrp + 16 * i] = s;
    }

    // ---- stage accumulators to smem (reuse A buffer 0) ----
    float* dotS = (float*)(smb + SM_A);          // 64 x 33 floats
    {
        const int g = lane >> 2, t = lane & 3;
        #pragma unroll
        for (int n = 0; n < 4; n++) {
            int r0 = 16 * wid + g, c = n * 8 + t * 2;
            dotS[r0 * 33 + c]       = acc[n][0];
            dotS[r0 * 33 + c + 1]   = acc[n][1];
            dotS[(r0+8) * 33 + c]   = acc[n][2];
            dotS[(r0+8) * 33 + c+1] = acc[n][3];
        }
    }
    __syncthreads();

    // ---- epilogue: one thread per row ----
    if (tid < M_TILE) {
        const int row = tid;
        const float invD  = 1.0f / (float)D_IN;
        const float invDm = 1.0f / (float)(D_IN - 1);
        float mean = sumS[row] * invD;
        float var  = (sqS[row] - (float)D_IN * mean * mean) * invDm;
        float rstd = rsqrtf(var);

        float y[32];
        #pragma unroll
        for (int j = 0; j < 32; j++) {
            float d = dotS[row * 33 + j];
            float v = fmaf(d - mean * ScS[j], rstd, b1S[j]);
            y[j] = fmaxf(v, 0.01f * v);
        }
        float a2[32];
        #pragma unroll
        for (int j = 0; j < 32; j++) {
            float s = b2S[j];
            #pragma unroll
            for (int i = 0; i < 32; i++) s = fmaf(w2S[j * 32 + i], y[i], s);
            a2[j] = fmaxf(s, 0.01f * s);
        }
        float a3[OUT_N];
        #pragma unroll
        for (int j = 0; j < OUT_N; j++) {
            float s = b3S[j];
            #pragma unroll
            for (int i = 0; i < 32; i++) s = fmaf(w3S[j * 32 + i], a2[i], s);
            a3[j] = fmaxf(s, 0.01f * s);
        }
        float* op = out + (rowbase + row) * OUT_N;
        #pragma unroll
        for (int j = 0; j < OUT_N; j += 2)
            *(float2*)(op + j) = make_float2(a3[j], a3[j + 1]);
    }
}

// ---------------------------------------------------------------------------
extern "C" void kernel_launch(void* const* d_in, const int* in_sizes, int n_in,
                              void* d_out, int out_size) {
    const float* x  = (const float*)d_in[0];
    const float* w1 = (const float*)d_in[1];
    const float* b1 = (const float*)d_in[2];
    const float* w2 = (const float*)d_in[3];
    const float* b2 = (const float*)d_in[4];
    const float* w3 = (const float*)d_in[5];
    const float* b3 = (const float*)d_in[6];
    float* out = (float*)d_out;

    static bool attr_set = false;
    if (!attr_set) {
        cudaFuncSetAttribute(fused_kernel,
                             cudaFuncAttributeMaxDynamicSharedMemorySize, SM_BYTES);
        attr_set = true;
    }

    fused_kernel<<<N_ROWS / M_TILE, NT, SM_BYTES>>>(x, w1, b1, w2, b2, w3, b3, out);
}